// round 1
// baseline (speedup 1.0000x reference)
#include <cuda_runtime.h>
#include <cuda_bf16.h>
#include <math.h>

// ---------------- problem constants ----------------
#define B_     2
#define C_     256
#define N_     32768
#define H_     128
#define W_     128
#define HW_    16384
#define NG_    3
#define DEPTH_ 4

// ---------------- device scratch (static, no allocs) ----------------
__device__ float g_grid [B_*C_*HW_];   // scatter grid / conv input
__device__ float g_plane[B_*C_*HW_];   // conv output (rflat)
__device__ float g_skip [B_*C_*HW_];   // plane snapshot from depth 0 (grid 0)
__device__ float g_wpt  [B_*NG_*N_];
__device__ int   g_ci   [B_*NG_*N_];
__device__ float g_counts[B_*NG_*HW_];
__device__ float g_bnm[C_];
__device__ float g_bnr[C_];

// ---------------- simple copies ----------------
__global__ void copy4_kernel(const float4* __restrict__ src, float4* __restrict__ dst, int n4) {
    int i = blockIdx.x * blockDim.x + threadIdx.x;
    if (i < n4) dst[i] = src[i];
}

__global__ void save_skip_kernel() {
    int i = blockIdx.x * blockDim.x + threadIdx.x;   // float4 index
    reinterpret_cast<float4*>(g_skip)[i] = reinterpret_cast<const float4*>(g_plane)[i];
}

__global__ void grid_init_kernel(int use_skip) {
    int i = blockIdx.x * blockDim.x + threadIdx.x;   // float4 index
    float4 v;
    if (use_skip) v = reinterpret_cast<const float4*>(g_skip)[i];
    else          v = make_float4(0.f, 0.f, 0.f, 0.f);
    reinterpret_cast<float4*>(g_grid)[i] = v;
}

// ---------------- projection weights (once) ----------------
__global__ void zero_counts_kernel() {
    int i = blockIdx.x * blockDim.x + threadIdx.x;
    if (i < B_*NG_*HW_) g_counts[i] = 0.f;
}

__global__ void count_scatter_kernel(const int* __restrict__ cell_ind,
                                     const float* __restrict__ occ) {
    int i = blockIdx.x * blockDim.x + threadIdx.x;   // over B*NG*N
    if (i >= B_*NG_*N_) return;
    int n = i % N_;
    int g = (i / N_) % NG_;
    int b = i / (NG_*N_);
    int ci = cell_ind[i];
    ci = min(max(ci, 0), HW_ - 1);
    g_ci[i] = ci;
    float o = occ[b*N_ + n];
    atomicAdd(&g_counts[(b*NG_ + g)*HW_ + ci], o*o);
}

__global__ void wpt_kernel(const float* __restrict__ occ) {
    int i = blockIdx.x * blockDim.x + threadIdx.x;
    if (i >= B_*NG_*N_) return;
    int n = i % N_;
    int g = (i / N_) % NG_;
    int b = i / (NG_*N_);
    float o = occ[b*N_ + n];
    float cnt = g_counts[(b*NG_ + g)*HW_ + g_ci[i]];
    g_wpt[i] = o / (o*cnt + 1e-6f);
}

// ---------------- SpatialMix: LN over channels + weighted scatter ----------------
__global__ void ln_scatter_kernel(const float* __restrict__ tokens,
                                  const float* __restrict__ lng,
                                  const float* __restrict__ lnb,
                                  int g) {
    __shared__ float sg[C_], sb[C_];
    int tid = threadIdx.x;
    sg[tid] = lng[tid];
    sb[tid] = lnb[tid];
    __syncthreads();

    int b = blockIdx.y;
    int n = blockIdx.x * 256 + tid;
    const float* tb = tokens + (size_t)b*C_*N_ + n;

    float s = 0.f, ss = 0.f;
    #pragma unroll 8
    for (int c = 0; c < C_; c++) {
        float x = tb[(size_t)c * N_];
        s += x; ss += x * x;
    }
    float m = s * (1.f / C_);
    float rstd = rsqrtf(ss * (1.f / C_) - m*m + 1e-5f);

    int   cell = g_ci [((size_t)b*NG_ + g)*N_ + n];
    float w    = g_wpt[((size_t)b*NG_ + g)*N_ + n];
    float* gb = g_grid + (size_t)b*C_*HW_ + cell;
    #pragma unroll 4
    for (int c = 0; c < C_; c++) {
        float x = tb[(size_t)c * N_];
        float v = ((x - m) * rstd * sg[c] + sb[c]) * w;
        atomicAdd(gb + (size_t)c * HW_, v);
    }
}

// ---------------- fused depthwise conv3x3 -> relu -> conv3x3 ----------------
#define CONV_SMEM (2 * 130 * 132 * 4)
__global__ void dwconv2_kernel(const float* __restrict__ w1, const float* __restrict__ b1,
                               const float* __restrict__ w2, const float* __restrict__ b2) {
    extern __shared__ float sm[];
    float* s0 = sm;                 // [130][132] zero-padded input
    float* s1 = sm + 130 * 132;     // [130][132] zero-padded mid

    int bc = blockIdx.x;            // b*C + c
    int c  = bc % C_;
    const float* img = g_grid + (size_t)bc * HW_;
    float* out = g_plane + (size_t)bc * HW_;

    for (int i = threadIdx.x; i < 130*132*2; i += blockDim.x) sm[i] = 0.f;
    __syncthreads();
    for (int i = threadIdx.x; i < HW_; i += blockDim.x) {
        int y = i >> 7, x = i & 127;
        s0[(y+1)*132 + (x+1)] = img[i];
    }
    float w[9];
    #pragma unroll
    for (int j = 0; j < 9; j++) w[j] = __ldg(w1 + c*9 + j);
    float bb = __ldg(b1 + c);
    __syncthreads();

    for (int i = threadIdx.x; i < HW_; i += blockDim.x) {
        int y = i >> 7, x = i & 127;
        const float* p = &s0[y*132 + x];
        float acc = bb;
        acc += w[0]*p[0]   + w[1]*p[1]   + w[2]*p[2];
        acc += w[3]*p[132] + w[4]*p[133] + w[5]*p[134];
        acc += w[6]*p[264] + w[7]*p[265] + w[8]*p[266];
        s1[(y+1)*132 + (x+1)] = fmaxf(acc, 0.f);
    }
    #pragma unroll
    for (int j = 0; j < 9; j++) w[j] = __ldg(w2 + c*9 + j);
    bb = __ldg(b2 + c);
    __syncthreads();

    for (int i = threadIdx.x; i < HW_; i += blockDim.x) {
        int y = i >> 7, x = i & 127;
        const float* p = &s1[y*132 + x];
        float acc = bb;
        acc += w[0]*p[0]   + w[1]*p[1]   + w[2]*p[2];
        acc += w[3]*p[132] + w[4]*p[133] + w[5]*p[134];
        acc += w[6]*p[264] + w[7]*p[265] + w[8]*p[266];
        out[i] = acc;
    }
}

// ---------------- BatchNorm (train-mode batch stats), two-pass ----------------
__global__ void bn_stats_kernel(const float* __restrict__ ascale) {
    int c = blockIdx.x;
    float s = __ldg(ascale + c);
    __shared__ float rbuf[256];
    __shared__ float mean_sh;

    float sum = 0.f;
    for (int b = 0; b < B_; b++) {
        const float* p = g_plane + ((size_t)b*C_ + c) * HW_;
        for (int i = threadIdx.x; i < HW_; i += 256) sum += p[i] * s;
    }
    rbuf[threadIdx.x] = sum; __syncthreads();
    for (int o = 128; o > 0; o >>= 1) {
        if (threadIdx.x < o) rbuf[threadIdx.x] += rbuf[threadIdx.x + o];
        __syncthreads();
    }
    if (threadIdx.x == 0) mean_sh = rbuf[0] * (1.f / (B_*HW_));
    __syncthreads();
    float m = mean_sh;

    float vs = 0.f;
    for (int b = 0; b < B_; b++) {
        const float* p = g_plane + ((size_t)b*C_ + c) * HW_;
        for (int i = threadIdx.x; i < HW_; i += 256) {
            float d = p[i] * s - m;
            vs += d * d;
        }
    }
    rbuf[threadIdx.x] = vs; __syncthreads();
    for (int o = 128; o > 0; o >>= 1) {
        if (threadIdx.x < o) rbuf[threadIdx.x] += rbuf[threadIdx.x + o];
        __syncthreads();
    }
    if (threadIdx.x == 0) {
        g_bnm[c] = m;
        g_bnr[c] = rsqrtf(rbuf[0] * (1.f / (B_*HW_)) + 1e-5f);
    }
}

// ---------------- sigmoid gate + gather + residual add ----------------
__global__ void gather_update_kernel(float* __restrict__ tokens, int g,
                                     const float* __restrict__ ascale,
                                     const float* __restrict__ bng,
                                     const float* __restrict__ bnb) {
    int n = blockIdx.x * 256 + threadIdx.x;
    int c = blockIdx.y;
    int b = blockIdx.z;
    int cell = g_ci[((size_t)b*NG_ + g)*N_ + n];
    float p = g_plane[((size_t)b*C_ + c)*HW_ + cell];
    float y = p * __ldg(ascale + c);
    float t = (y - g_bnm[c]) * g_bnr[c] * __ldg(bng + c) + __ldg(bnb + c);
    float att = 1.f / (1.f + expf(-t));
    tokens[((size_t)b*C_ + c)*N_ + n] += att * p;
}

// ---------------- fused ChannelMix: LN -> W1+b1 -> relu -> W2+b2 -> scaled residual ----------------
#define CM_NT 128
#define CM_WS 258
#define CM_SMEM ((C_*CM_NT + 16*CM_WS + 512 + 512 + 128 + 128 + 256 + 256) * 4)

__global__ void __launch_bounds__(512, 1)
channelmix_kernel(float* __restrict__ tokens,
                  const float* __restrict__ lng, const float* __restrict__ lnb,
                  const float* __restrict__ W1,  const float* __restrict__ b1,
                  const float* __restrict__ W2,  const float* __restrict__ b2,
                  const float* __restrict__ csc) {
    extern __shared__ float sm[];
    float* Xs     = sm;                       // [256][128]
    float* Ws     = Xs + C_*CM_NT;            // [16][258]
    float* red    = Ws + 16*CM_WS;            // [4][128]
    float* red2   = red + 512;                // [4][128]
    float* mean_s = red2 + 512;               // [128]
    float* rstd_s = mean_s + 128;             // [128]
    float* lg     = rstd_s + 128;             // [256]
    float* lb     = lg + 256;                 // [256]

    const int tid = threadIdx.x;
    const int b   = blockIdx.y;
    const int n0  = blockIdx.x * CM_NT;

    // load tokens tile [256 x 128] (coalesced float4)
    for (int i = tid; i < (C_*CM_NT)/4; i += 512) {
        int k  = i >> 5;        // row (channel)
        int nv = i & 31;        // float4 within row
        float4 v = *reinterpret_cast<const float4*>(tokens + ((size_t)b*C_ + k)*N_ + n0 + nv*4);
        reinterpret_cast<float4*>(Xs)[(k << 5) + nv] = v;
    }
    if (tid < 256) { lg[tid] = lng[tid]; lb[tid] = lnb[tid]; }
    __syncthreads();

    // LayerNorm over channels (per column)
    {
        int col = tid & 127, part = tid >> 7;
        float s = 0.f, ss = 0.f;
        int k0 = part * 64;
        #pragma unroll 4
        for (int k = k0; k < k0 + 64; k++) {
            float x = Xs[k*CM_NT + col];
            s += x; ss += x*x;
        }
        red [part*128 + col] = s;
        red2[part*128 + col] = ss;
    }
    __syncthreads();
    if (tid < 128) {
        float s  = red [tid] + red [128+tid] + red [256+tid] + red [384+tid];
        float ss = red2[tid] + red2[128+tid] + red2[256+tid] + red2[384+tid];
        float m = s * (1.f / C_);
        float v = ss * (1.f / C_) - m*m;
        mean_s[tid] = m;
        rstd_s[tid] = rsqrtf(v + 1e-5f);
    }
    __syncthreads();
    for (int i = tid; i < C_*CM_NT; i += 512) {
        int k = i >> 7, col = i & 127;
        Xs[i] = (Xs[i] - mean_s[col]) * rstd_s[col] * lg[k] + lb[k];
    }
    __syncthreads();

    const int tx = tid & 15;     // n tile: 8 cols
    const int ty = tid >> 4;     // m tile: 8 rows
    float acc[8][8];

    // ================= GEMM 1 =================
    #pragma unroll
    for (int i = 0; i < 8; i++)
        #pragma unroll
        for (int j = 0; j < 8; j++) acc[i][j] = 0.f;

    for (int k0 = 0; k0 < C_; k0 += 16) {
        {   // stage W1[k0:k0+16][:] transposed into Ws[kk][m]
            int m   = tid >> 1;
            int kk0 = (tid & 1) << 3;
            const float4* wr = reinterpret_cast<const float4*>(W1 + m*C_ + k0 + kk0);
            float4 a = wr[0], c4 = wr[1];
            Ws[(kk0+0)*CM_WS + m] = a.x;  Ws[(kk0+1)*CM_WS + m] = a.y;
            Ws[(kk0+2)*CM_WS + m] = a.z;  Ws[(kk0+3)*CM_WS + m] = a.w;
            Ws[(kk0+4)*CM_WS + m] = c4.x; Ws[(kk0+5)*CM_WS + m] = c4.y;
            Ws[(kk0+6)*CM_WS + m] = c4.z; Ws[(kk0+7)*CM_WS + m] = c4.w;
        }
        __syncthreads();
        #pragma unroll
        for (int kk = 0; kk < 16; kk++) {
            float xf[8], wf[8];
            float4 x0 = *reinterpret_cast<float4*>(&Xs[(k0+kk)*CM_NT + tx*8]);
            float4 x1 = *reinterpret_cast<float4*>(&Xs[(k0+kk)*CM_NT + tx*8 + 4]);
            xf[0]=x0.x; xf[1]=x0.y; xf[2]=x0.z; xf[3]=x0.w;
            xf[4]=x1.x; xf[5]=x1.y; xf[6]=x1.z; xf[7]=x1.w;
            #pragma unroll
            for (int i = 0; i < 8; i++) wf[i] = Ws[kk*CM_WS + ty*8 + i];
            #pragma unroll
            for (int i = 0; i < 8; i++)
                #pragma unroll
                for (int j = 0; j < 8; j++)
                    acc[i][j] = fmaf(wf[i], xf[j], acc[i][j]);
        }
        __syncthreads();
    }

    // relu(h1 + b1) back into Xs
    #pragma unroll
    for (int i = 0; i < 8; i++) {
        int m = ty*8 + i;
        float bv = __ldg(b1 + m);
        float4 v0, v1;
        v0.x = fmaxf(acc[i][0]+bv, 0.f); v0.y = fmaxf(acc[i][1]+bv, 0.f);
        v0.z = fmaxf(acc[i][2]+bv, 0.f); v0.w = fmaxf(acc[i][3]+bv, 0.f);
        v1.x = fmaxf(acc[i][4]+bv, 0.f); v1.y = fmaxf(acc[i][5]+bv, 0.f);
        v1.z = fmaxf(acc[i][6]+bv, 0.f); v1.w = fmaxf(acc[i][7]+bv, 0.f);
        *reinterpret_cast<float4*>(&Xs[m*CM_NT + tx*8])     = v0;
        *reinterpret_cast<float4*>(&Xs[m*CM_NT + tx*8 + 4]) = v1;
    }
    __syncthreads();

    // ================= GEMM 2 =================
    #pragma unroll
    for (int i = 0; i < 8; i++)
        #pragma unroll
        for (int j = 0; j < 8; j++) acc[i][j] = 0.f;

    for (int k0 = 0; k0 < C_; k0 += 16) {
        {
            int m   = tid >> 1;
            int kk0 = (tid & 1) << 3;
            const float4* wr = reinterpret_cast<const float4*>(W2 + m*C_ + k0 + kk0);
            float4 a = wr[0], c4 = wr[1];
            Ws[(kk0+0)*CM_WS + m] = a.x;  Ws[(kk0+1)*CM_WS + m] = a.y;
            Ws[(kk0+2)*CM_WS + m] = a.z;  Ws[(kk0+3)*CM_WS + m] = a.w;
            Ws[(kk0+4)*CM_WS + m] = c4.x; Ws[(kk0+5)*CM_WS + m] = c4.y;
            Ws[(kk0+6)*CM_WS + m] = c4.z; Ws[(kk0+7)*CM_WS + m] = c4.w;
        }
        __syncthreads();
        #pragma unroll
        for (int kk = 0; kk < 16; kk++) {
            float xf[8], wf[8];
            float4 x0 = *reinterpret_cast<float4*>(&Xs[(k0+kk)*CM_NT + tx*8]);
            float4 x1 = *reinterpret_cast<float4*>(&Xs[(k0+kk)*CM_NT + tx*8 + 4]);
            xf[0]=x0.x; xf[1]=x0.y; xf[2]=x0.z; xf[3]=x0.w;
            xf[4]=x1.x; xf[5]=x1.y; xf[6]=x1.z; xf[7]=x1.w;
            #pragma unroll
            for (int i = 0; i < 8; i++) wf[i] = Ws[kk*CM_WS + ty*8 + i];
            #pragma unroll
            for (int i = 0; i < 8; i++)
                #pragma unroll
                for (int j = 0; j < 8; j++)
                    acc[i][j] = fmaf(wf[i], xf[j], acc[i][j]);
        }
        __syncthreads();
    }

    // tokens += (h2 + b2) * scale
    #pragma unroll
    for (int i = 0; i < 8; i++) {
        int m = ty*8 + i;
        float bv = __ldg(b2 + m);
        float sc = __ldg(csc + m);
        float* trow = tokens + ((size_t)b*C_ + m)*N_ + n0 + tx*8;
        float4 t0 = *reinterpret_cast<float4*>(trow);
        float4 t1 = *reinterpret_cast<float4*>(trow + 4);
        t0.x += (acc[i][0]+bv)*sc; t0.y += (acc[i][1]+bv)*sc;
        t0.z += (acc[i][2]+bv)*sc; t0.w += (acc[i][3]+bv)*sc;
        t1.x += (acc[i][4]+bv)*sc; t1.y += (acc[i][5]+bv)*sc;
        t1.z += (acc[i][6]+bv)*sc; t1.w += (acc[i][7]+bv)*sc;
        *reinterpret_cast<float4*>(trow)     = t0;
        *reinterpret_cast<float4*>(trow + 4) = t1;
    }
}

// ---------------- launch ----------------
extern "C" void kernel_launch(void* const* d_in, const int* in_sizes, int n_in,
                              void* d_out, int out_size) {
    const float* tokens_in  = (const float*)d_in[0];
    const int*   cell_ind   = (const int*)  d_in[1];
    const float* occ        = (const float*)d_in[2];
    const float* smix_ln_g  = (const float*)d_in[3];
    const float* smix_ln_b  = (const float*)d_in[4];
    const float* ffn_w1     = (const float*)d_in[5];
    const float* ffn_b1     = (const float*)d_in[6];
    const float* ffn_w2     = (const float*)d_in[7];
    const float* ffn_b2     = (const float*)d_in[8];
    const float* att_scale  = (const float*)d_in[9];
    const float* att_bn_g   = (const float*)d_in[10];
    const float* att_bn_b   = (const float*)d_in[11];
    const float* cmix_ln_g  = (const float*)d_in[12];
    const float* cmix_ln_b  = (const float*)d_in[13];
    const float* cmix_w1    = (const float*)d_in[14];
    const float* cmix_b1    = (const float*)d_in[15];
    const float* cmix_w2    = (const float*)d_in[16];
    const float* cmix_b2    = (const float*)d_in[17];
    const float* cmix_scale = (const float*)d_in[18];
    float* tokens = (float*)d_out;

    cudaFuncSetAttribute(dwconv2_kernel,    cudaFuncAttributeMaxDynamicSharedMemorySize, CONV_SMEM);
    cudaFuncSetAttribute(channelmix_kernel, cudaFuncAttributeMaxDynamicSharedMemorySize, CM_SMEM);

    // tokens -> d_out (working buffer)
    copy4_kernel<<<(B_*C_*N_/4 + 255)/256, 256>>>(
        reinterpret_cast<const float4*>(tokens_in),
        reinterpret_cast<float4*>(tokens), B_*C_*N_/4);

    // projection weights (fixed across depths)
    zero_counts_kernel <<<(B_*NG_*HW_ + 255)/256, 256>>>();
    count_scatter_kernel<<<(B_*NG_*N_ + 255)/256, 256>>>(cell_ind, occ);
    wpt_kernel          <<<(B_*NG_*N_ + 255)/256, 256>>>(occ);

    for (int d = 0; d < DEPTH_; d++) {
        int g = d % NG_;
        // grid = skip (only depth 3, grid 0 has a non-zero skip = depth-0 plane) else 0
        grid_init_kernel<<<(B_*C_*HW_/4)/256, 256>>>((d == 3 && g == 0) ? 1 : 0);

        ln_scatter_kernel<<<dim3(N_/256, B_), 256>>>(tokens, smix_ln_g + d*C_, smix_ln_b + d*C_, g);

        dwconv2_kernel<<<B_*C_, 256, CONV_SMEM>>>(ffn_w1 + d*C_*9, ffn_b1 + d*C_,
                                                  ffn_w2 + d*C_*9, ffn_b2 + d*C_);
        if (d == 0) save_skip_kernel<<<(B_*C_*HW_/4)/256, 256>>>();

        bn_stats_kernel<<<C_, 256>>>(att_scale + d*C_);

        gather_update_kernel<<<dim3(N_/256, C_, B_), 256>>>(tokens, g,
                                                            att_scale + d*C_,
                                                            att_bn_g + d*C_,
                                                            att_bn_b + d*C_);

        channelmix_kernel<<<dim3(N_/CM_NT, B_), 512, CM_SMEM>>>(
            tokens,
            cmix_ln_g + d*C_, cmix_ln_b + d*C_,
            cmix_w1 + d*C_*C_, cmix_b1 + d*C_,
            cmix_w2 + d*C_*C_, cmix_b2 + d*C_,
            cmix_scale + d*C_);
    }
}

// round 2
// speedup vs baseline: 1.3855x; 1.3855x over previous
#include <cuda_runtime.h>
#include <cuda_bf16.h>
#include <math.h>
#include <stdint.h>

// ---------------- problem constants ----------------
#define B_     2
#define C_     256
#define N_     32768
#define H_     128
#define W_     128
#define HW_    16384
#define NG_    3
#define DEPTH_ 4

// ---------------- device scratch (static, no allocs) ----------------
__device__ float g_grid [B_*C_*HW_];   // scatter grid / conv input
__device__ float g_plane[B_*C_*HW_];   // conv output (rflat)
__device__ float g_skip [B_*C_*HW_];   // plane snapshot from depth 0 (grid 0)
__device__ float g_wpt  [B_*NG_*N_];
__device__ int   g_ci   [B_*NG_*N_];
__device__ float g_counts[B_*NG_*HW_];
__device__ float g_bnm[C_];
__device__ float g_bnr[C_];

// ---------------- helpers ----------------
__device__ __forceinline__ float to_tf32(float x) {
    float r;
    asm("cvt.rna.tf32.f32 %0, %1;" : "=f"(r) : "f"(x));
    return r;
}

__device__ __forceinline__ void mma_tf32(float d[4], const uint32_t a[4], const uint32_t b[2]) {
    asm volatile(
        "mma.sync.aligned.m16n8k8.row.col.f32.tf32.tf32.f32 "
        "{%0,%1,%2,%3}, {%4,%5,%6,%7}, {%8,%9}, {%0,%1,%2,%3};\n"
        : "+f"(d[0]), "+f"(d[1]), "+f"(d[2]), "+f"(d[3])
        : "r"(a[0]), "r"(a[1]), "r"(a[2]), "r"(a[3]),
          "r"(b[0]), "r"(b[1]));
}

// ---------------- simple copies ----------------
__global__ void copy4_kernel(const float4* __restrict__ src, float4* __restrict__ dst, int n4) {
    int i = blockIdx.x * blockDim.x + threadIdx.x;
    if (i < n4) dst[i] = src[i];
}

__global__ void save_skip_kernel() {
    int i = blockIdx.x * blockDim.x + threadIdx.x;   // float4 index
    reinterpret_cast<float4*>(g_skip)[i] = reinterpret_cast<const float4*>(g_plane)[i];
}

__global__ void grid_init_kernel(int use_skip) {
    int i = blockIdx.x * blockDim.x + threadIdx.x;   // float4 index
    float4 v;
    if (use_skip) v = reinterpret_cast<const float4*>(g_skip)[i];
    else          v = make_float4(0.f, 0.f, 0.f, 0.f);
    reinterpret_cast<float4*>(g_grid)[i] = v;
}

// ---------------- projection weights (once) ----------------
__global__ void zero_counts_kernel() {
    int i = blockIdx.x * blockDim.x + threadIdx.x;
    if (i < B_*NG_*HW_) g_counts[i] = 0.f;
}

__global__ void count_scatter_kernel(const int* __restrict__ cell_ind,
                                     const float* __restrict__ occ) {
    int i = blockIdx.x * blockDim.x + threadIdx.x;   // over B*NG*N
    if (i >= B_*NG_*N_) return;
    int n = i % N_;
    int g = (i / N_) % NG_;
    int b = i / (NG_*N_);
    int ci = cell_ind[i];
    ci = min(max(ci, 0), HW_ - 1);
    g_ci[i] = ci;
    float o = occ[b*N_ + n];
    atomicAdd(&g_counts[(b*NG_ + g)*HW_ + ci], o*o);
}

__global__ void wpt_kernel(const float* __restrict__ occ) {
    int i = blockIdx.x * blockDim.x + threadIdx.x;
    if (i >= B_*NG_*N_) return;
    int n = i % N_;
    int g = (i / N_) % NG_;
    int b = i / (NG_*N_);
    float o = occ[b*N_ + n];
    float cnt = g_counts[(b*NG_ + g)*HW_ + g_ci[i]];
    g_wpt[i] = o / (o*cnt + 1e-6f);
}

// ---------------- SpatialMix: LN over channels + weighted scatter ----------------
__global__ void ln_scatter_kernel(const float* __restrict__ tokens,
                                  const float* __restrict__ lng,
                                  const float* __restrict__ lnb,
                                  int g) {
    __shared__ float sg[C_], sb[C_];
    int tid = threadIdx.x;
    sg[tid] = lng[tid];
    sb[tid] = lnb[tid];
    __syncthreads();

    int b = blockIdx.y;
    int n = blockIdx.x * 256 + tid;
    const float* tb = tokens + (size_t)b*C_*N_ + n;

    float s = 0.f, ss = 0.f;
    #pragma unroll 8
    for (int c = 0; c < C_; c++) {
        float x = tb[(size_t)c * N_];
        s += x; ss += x * x;
    }
    float m = s * (1.f / C_);
    float rstd = rsqrtf(ss * (1.f / C_) - m*m + 1e-5f);

    int   cell = g_ci [((size_t)b*NG_ + g)*N_ + n];
    float w    = g_wpt[((size_t)b*NG_ + g)*N_ + n];
    float* gb = g_grid + (size_t)b*C_*HW_ + cell;
    #pragma unroll 4
    for (int c = 0; c < C_; c++) {
        float x = tb[(size_t)c * N_];
        float v = ((x - m) * rstd * sg[c] + sb[c]) * w;
        atomicAdd(gb + (size_t)c * HW_, v);
    }
}

// ---------------- fused depthwise conv3x3 -> relu -> conv3x3 ----------------
#define CONV_SMEM (2 * 130 * 132 * 4)
__global__ void dwconv2_kernel(const float* __restrict__ w1, const float* __restrict__ b1,
                               const float* __restrict__ w2, const float* __restrict__ b2) {
    extern __shared__ float sm[];
    float* s0 = sm;                 // [130][132] zero-padded input
    float* s1 = sm + 130 * 132;     // [130][132] zero-padded mid

    int bc = blockIdx.x;            // b*C + c
    int c  = bc % C_;
    const float* img = g_grid + (size_t)bc * HW_;
    float* out = g_plane + (size_t)bc * HW_;

    for (int i = threadIdx.x; i < 130*132*2; i += blockDim.x) sm[i] = 0.f;
    __syncthreads();
    for (int i = threadIdx.x; i < HW_; i += blockDim.x) {
        int y = i >> 7, x = i & 127;
        s0[(y+1)*132 + (x+1)] = img[i];
    }
    float w[9];
    #pragma unroll
    for (int j = 0; j < 9; j++) w[j] = __ldg(w1 + c*9 + j);
    float bb = __ldg(b1 + c);
    __syncthreads();

    for (int i = threadIdx.x; i < HW_; i += blockDim.x) {
        int y = i >> 7, x = i & 127;
        const float* p = &s0[y*132 + x];
        float acc = bb;
        acc += w[0]*p[0]   + w[1]*p[1]   + w[2]*p[2];
        acc += w[3]*p[132] + w[4]*p[133] + w[5]*p[134];
        acc += w[6]*p[264] + w[7]*p[265] + w[8]*p[266];
        s1[(y+1)*132 + (x+1)] = fmaxf(acc, 0.f);
    }
    #pragma unroll
    for (int j = 0; j < 9; j++) w[j] = __ldg(w2 + c*9 + j);
    bb = __ldg(b2 + c);
    __syncthreads();

    for (int i = threadIdx.x; i < HW_; i += blockDim.x) {
        int y = i >> 7, x = i & 127;
        const float* p = &s1[y*132 + x];
        float acc = bb;
        acc += w[0]*p[0]   + w[1]*p[1]   + w[2]*p[2];
        acc += w[3]*p[132] + w[4]*p[133] + w[5]*p[134];
        acc += w[6]*p[264] + w[7]*p[265] + w[8]*p[266];
        out[i] = acc;
    }
}

// ---------------- BatchNorm (train-mode batch stats), two-pass ----------------
__global__ void bn_stats_kernel(const float* __restrict__ ascale) {
    int c = blockIdx.x;
    float s = __ldg(ascale + c);
    __shared__ float rbuf[256];
    __shared__ float mean_sh;

    float sum = 0.f;
    for (int b = 0; b < B_; b++) {
        const float* p = g_plane + ((size_t)b*C_ + c) * HW_;
        for (int i = threadIdx.x; i < HW_; i += 256) sum += p[i] * s;
    }
    rbuf[threadIdx.x] = sum; __syncthreads();
    for (int o = 128; o > 0; o >>= 1) {
        if (threadIdx.x < o) rbuf[threadIdx.x] += rbuf[threadIdx.x + o];
        __syncthreads();
    }
    if (threadIdx.x == 0) mean_sh = rbuf[0] * (1.f / (B_*HW_));
    __syncthreads();
    float m = mean_sh;

    float vs = 0.f;
    for (int b = 0; b < B_; b++) {
        const float* p = g_plane + ((size_t)b*C_ + c) * HW_;
        for (int i = threadIdx.x; i < HW_; i += 256) {
            float d = p[i] * s - m;
            vs += d * d;
        }
    }
    rbuf[threadIdx.x] = vs; __syncthreads();
    for (int o = 128; o > 0; o >>= 1) {
        if (threadIdx.x < o) rbuf[threadIdx.x] += rbuf[threadIdx.x + o];
        __syncthreads();
    }
    if (threadIdx.x == 0) {
        g_bnm[c] = m;
        g_bnr[c] = rsqrtf(rbuf[0] * (1.f / (B_*HW_)) + 1e-5f);
    }
}

// ---------------- sigmoid gate + gather + residual add ----------------
__global__ void gather_update_kernel(float* __restrict__ tokens, int g,
                                     const float* __restrict__ ascale,
                                     const float* __restrict__ bng,
                                     const float* __restrict__ bnb) {
    int n = blockIdx.x * 256 + threadIdx.x;
    int c = blockIdx.y;
    int b = blockIdx.z;
    int cell = g_ci[((size_t)b*NG_ + g)*N_ + n];
    float p = g_plane[((size_t)b*C_ + c)*HW_ + cell];
    float y = p * __ldg(ascale + c);
    float t = (y - g_bnm[c]) * g_bnr[c] * __ldg(bng + c) + __ldg(bnb + c);
    float att = 1.f / (1.f + expf(-t));
    tokens[((size_t)b*C_ + c)*N_ + n] += att * p;
}

// ---------------- tensor-core ChannelMix ----------------
// Block: 256 threads = 8 warps (4 m-warps x 2 n-warps), tile M=256 x NT=64.
// GEMM inner product via mma.sync.m16n8k8 tf32 (legacy HMMA path).
// SMEM padding chosen for conflict-free fragment LDS:
//   Xs stride 72  (72  mod 32 == 8  -> bank = 8*tig + gid, bijective in warp)
//   Ws stride 264 (264 mod 32 == 8)
#define CMT_NT     64
#define XS_STRIDE  72
#define WS_STRIDE  264
// floats: Xs 256*72 + Ws 16*264 + red 256 + red2 256 + mean 64 + rstd 64 + lg 256 + lb 256
#define CMT_SMEM   ((256*XS_STRIDE + 16*WS_STRIDE + 256 + 256 + 64 + 64 + 256 + 256) * 4)

__device__ __forceinline__ void cm_gemm_tc(const float* __restrict__ Wg,
                                           float* __restrict__ Xs, float* __restrict__ Ws,
                                           int tid, int gid, int tig, int wm, int wn,
                                           float acc[4][4][4]) {
    #pragma unroll
    for (int i = 0; i < 4; i++)
        #pragma unroll
        for (int j = 0; j < 4; j++)
            #pragma unroll
            for (int r = 0; r < 4; r++) acc[i][j][r] = 0.f;

    for (int k0 = 0; k0 < C_; k0 += 16) {
        // prefetch W chunk: row m = tid, cols k0..k0+15 (64B contiguous per thread)
        const float4* wr = reinterpret_cast<const float4*>(Wg + (size_t)tid*C_ + k0);
        float4 w0 = wr[0], w1 = wr[1], w2 = wr[2], w3 = wr[3];
        __syncthreads();   // previous chunk fully consumed
        Ws[ 0*WS_STRIDE + tid] = to_tf32(w0.x);
        Ws[ 1*WS_STRIDE + tid] = to_tf32(w0.y);
        Ws[ 2*WS_STRIDE + tid] = to_tf32(w0.z);
        Ws[ 3*WS_STRIDE + tid] = to_tf32(w0.w);
        Ws[ 4*WS_STRIDE + tid] = to_tf32(w1.x);
        Ws[ 5*WS_STRIDE + tid] = to_tf32(w1.y);
        Ws[ 6*WS_STRIDE + tid] = to_tf32(w1.z);
        Ws[ 7*WS_STRIDE + tid] = to_tf32(w1.w);
        Ws[ 8*WS_STRIDE + tid] = to_tf32(w2.x);
        Ws[ 9*WS_STRIDE + tid] = to_tf32(w2.y);
        Ws[10*WS_STRIDE + tid] = to_tf32(w2.z);
        Ws[11*WS_STRIDE + tid] = to_tf32(w2.w);
        Ws[12*WS_STRIDE + tid] = to_tf32(w3.x);
        Ws[13*WS_STRIDE + tid] = to_tf32(w3.y);
        Ws[14*WS_STRIDE + tid] = to_tf32(w3.z);
        Ws[15*WS_STRIDE + tid] = to_tf32(w3.w);
        __syncthreads();

        #pragma unroll
        for (int kk = 0; kk < 16; kk += 8) {
            uint32_t bfr[4][2];
            #pragma unroll
            for (int j = 0; j < 4; j++) {
                bfr[j][0] = __float_as_uint(Xs[(k0+kk+tig  )*XS_STRIDE + wn + j*8 + gid]);
                bfr[j][1] = __float_as_uint(Xs[(k0+kk+tig+4)*XS_STRIDE + wn + j*8 + gid]);
            }
            #pragma unroll
            for (int i = 0; i < 4; i++) {
                uint32_t afr[4];
                afr[0] = __float_as_uint(Ws[(kk+tig  )*WS_STRIDE + wm + i*16 + gid    ]);
                afr[1] = __float_as_uint(Ws[(kk+tig  )*WS_STRIDE + wm + i*16 + gid + 8]);
                afr[2] = __float_as_uint(Ws[(kk+tig+4)*WS_STRIDE + wm + i*16 + gid    ]);
                afr[3] = __float_as_uint(Ws[(kk+tig+4)*WS_STRIDE + wm + i*16 + gid + 8]);
                #pragma unroll
                for (int j = 0; j < 4; j++)
                    mma_tf32(acc[i][j], afr, bfr[j]);
            }
        }
    }
}

__global__ void __launch_bounds__(256, 2)
channelmix_tc_kernel(float* __restrict__ tokens,
                     const float* __restrict__ lng, const float* __restrict__ lnb,
                     const float* __restrict__ W1,  const float* __restrict__ b1,
                     const float* __restrict__ W2,  const float* __restrict__ b2,
                     const float* __restrict__ csc) {
    extern __shared__ float sm[];
    float* Xs     = sm;                         // [256][72]
    float* Ws     = Xs + 256*XS_STRIDE;         // [16][264]
    float* red    = Ws + 16*WS_STRIDE;          // [4][64]
    float* red2   = red + 256;                  // [4][64]
    float* mean_s = red2 + 256;                 // [64]
    float* rstd_s = mean_s + 64;                // [64]
    float* lg     = rstd_s + 64;                // [256]
    float* lb     = lg + 256;                   // [256]

    const int tid  = threadIdx.x;
    const int b    = blockIdx.y;
    const int n0   = blockIdx.x * CMT_NT;
    const int lane = tid & 31;
    const int wid  = tid >> 5;
    const int gid  = lane >> 2;
    const int tig  = lane & 3;
    const int wm   = (wid >> 1) * 64;   // warp m base
    const int wn   = (wid & 1)  * 32;   // warp n base

    // ---- load tokens tile [256 x 64] ----
    #pragma unroll
    for (int i = tid; i < 256*16; i += 256) {
        int k = i >> 4, f = i & 15;
        float4 v = *reinterpret_cast<const float4*>(tokens + ((size_t)b*C_ + k)*N_ + n0 + f*4);
        *reinterpret_cast<float4*>(&Xs[k*XS_STRIDE + f*4]) = v;
    }
    lg[tid] = lng[tid];
    lb[tid] = lnb[tid];
    __syncthreads();

    // ---- LayerNorm over channels per column ----
    {
        int col = tid & 63, part = tid >> 6;
        float s = 0.f, ss = 0.f;
        #pragma unroll 8
        for (int k = part*64; k < part*64 + 64; k++) {
            float x = Xs[k*XS_STRIDE + col];
            s += x; ss += x*x;
        }
        red [part*64 + col] = s;
        red2[part*64 + col] = ss;
    }
    __syncthreads();
    if (tid < 64) {
        float s  = red [tid] + red [64+tid] + red [128+tid] + red [192+tid];
        float ss = red2[tid] + red2[64+tid] + red2[128+tid] + red2[192+tid];
        float m = s * (1.f / C_);
        mean_s[tid] = m;
        rstd_s[tid] = rsqrtf(ss * (1.f / C_) - m*m + 1e-5f);
    }
    __syncthreads();
    for (int i = tid; i < 256*64; i += 256) {
        int k = i >> 6, col = i & 63;
        float v = (Xs[k*XS_STRIDE + col] - mean_s[col]) * rstd_s[col] * lg[k] + lb[k];
        Xs[k*XS_STRIDE + col] = to_tf32(v);
    }
    // (cm_gemm_tc starts with __syncthreads before first STS)

    float acc[4][4][4];

    // ---------------- GEMM 1 ----------------
    cm_gemm_tc(W1, Xs, Ws, tid, gid, tig, wm, wn, acc);

    __syncthreads();   // all Xs reads done before overwrite
    #pragma unroll
    for (int i = 0; i < 4; i++) {
        int m0 = wm + i*16 + gid;
        float bva = __ldg(b1 + m0);
        float bvb = __ldg(b1 + m0 + 8);
        #pragma unroll
        for (int j = 0; j < 4; j++) {
            int col = wn + j*8 + 2*tig;
            Xs[ m0    *XS_STRIDE + col    ] = to_tf32(fmaxf(acc[i][j][0] + bva, 0.f));
            Xs[ m0    *XS_STRIDE + col + 1] = to_tf32(fmaxf(acc[i][j][1] + bva, 0.f));
            Xs[(m0+8) *XS_STRIDE + col    ] = to_tf32(fmaxf(acc[i][j][2] + bvb, 0.f));
            Xs[(m0+8) *XS_STRIDE + col + 1] = to_tf32(fmaxf(acc[i][j][3] + bvb, 0.f));
        }
    }

    // ---------------- GEMM 2 ----------------
    cm_gemm_tc(W2, Xs, Ws, tid, gid, tig, wm, wn, acc);

    // ---- tokens += (h2 + b2) * scale ----
    #pragma unroll
    for (int i = 0; i < 4; i++) {
        int m0 = wm + i*16 + gid;
        float b2a = __ldg(b2 + m0),     sca = __ldg(csc + m0);
        float b2b = __ldg(b2 + m0 + 8), scb = __ldg(csc + m0 + 8);
        #pragma unroll
        for (int j = 0; j < 4; j++) {
            int col = wn + j*8 + 2*tig;
            float* p0 = tokens + ((size_t)b*C_ + m0    )*N_ + n0 + col;
            float* p1 = tokens + ((size_t)b*C_ + m0 + 8)*N_ + n0 + col;
            float2 t0 = *reinterpret_cast<float2*>(p0);
            float2 t1 = *reinterpret_cast<float2*>(p1);
            t0.x += (acc[i][j][0] + b2a) * sca;
            t0.y += (acc[i][j][1] + b2a) * sca;
            t1.x += (acc[i][j][2] + b2b) * scb;
            t1.y += (acc[i][j][3] + b2b) * scb;
            *reinterpret_cast<float2*>(p0) = t0;
            *reinterpret_cast<float2*>(p1) = t1;
        }
    }
}

// ---------------- launch ----------------
extern "C" void kernel_launch(void* const* d_in, const int* in_sizes, int n_in,
                              void* d_out, int out_size) {
    const float* tokens_in  = (const float*)d_in[0];
    const int*   cell_ind   = (const int*)  d_in[1];
    const float* occ        = (const float*)d_in[2];
    const float* smix_ln_g  = (const float*)d_in[3];
    const float* smix_ln_b  = (const float*)d_in[4];
    const float* ffn_w1     = (const float*)d_in[5];
    const float* ffn_b1     = (const float*)d_in[6];
    const float* ffn_w2     = (const float*)d_in[7];
    const float* ffn_b2     = (const float*)d_in[8];
    const float* att_scale  = (const float*)d_in[9];
    const float* att_bn_g   = (const float*)d_in[10];
    const float* att_bn_b   = (const float*)d_in[11];
    const float* cmix_ln_g  = (const float*)d_in[12];
    const float* cmix_ln_b  = (const float*)d_in[13];
    const float* cmix_w1    = (const float*)d_in[14];
    const float* cmix_b1    = (const float*)d_in[15];
    const float* cmix_w2    = (const float*)d_in[16];
    const float* cmix_b2    = (const float*)d_in[17];
    const float* cmix_scale = (const float*)d_in[18];
    float* tokens = (float*)d_out;

    cudaFuncSetAttribute(dwconv2_kernel,       cudaFuncAttributeMaxDynamicSharedMemorySize, CONV_SMEM);
    cudaFuncSetAttribute(channelmix_tc_kernel, cudaFuncAttributeMaxDynamicSharedMemorySize, CMT_SMEM);

    // tokens -> d_out (working buffer)
    copy4_kernel<<<(B_*C_*N_/4 + 255)/256, 256>>>(
        reinterpret_cast<const float4*>(tokens_in),
        reinterpret_cast<float4*>(tokens), B_*C_*N_/4);

    // projection weights (fixed across depths)
    zero_counts_kernel <<<(B_*NG_*HW_ + 255)/256, 256>>>();
    count_scatter_kernel<<<(B_*NG_*N_ + 255)/256, 256>>>(cell_ind, occ);
    wpt_kernel          <<<(B_*NG_*N_ + 255)/256, 256>>>(occ);

    for (int d = 0; d < DEPTH_; d++) {
        int g = d % NG_;
        // grid = skip (only depth 3 / grid 0 has non-zero skip = depth-0 plane) else 0
        grid_init_kernel<<<(B_*C_*HW_/4)/256, 256>>>((d == 3 && g == 0) ? 1 : 0);

        ln_scatter_kernel<<<dim3(N_/256, B_), 256>>>(tokens, smix_ln_g + d*C_, smix_ln_b + d*C_, g);

        dwconv2_kernel<<<B_*C_, 256, CONV_SMEM>>>(ffn_w1 + d*C_*9, ffn_b1 + d*C_,
                                                  ffn_w2 + d*C_*9, ffn_b2 + d*C_);
        if (d == 0) save_skip_kernel<<<(B_*C_*HW_/4)/256, 256>>>();

        bn_stats_kernel<<<C_, 256>>>(att_scale + d*C_);

        gather_update_kernel<<<dim3(N_/256, C_, B_), 256>>>(tokens, g,
                                                            att_scale + d*C_,
                                                            att_bn_g + d*C_,
                                                            att_bn_b + d*C_);

        channelmix_tc_kernel<<<dim3(N_/CMT_NT, B_), 256, CMT_SMEM>>>(
            tokens,
            cmix_ln_g + d*C_, cmix_ln_b + d*C_,
            cmix_w1 + d*C_*C_, cmix_b1 + d*C_,
            cmix_w2 + d*C_*C_, cmix_b2 + d*C_,
            cmix_scale + d*C_);
    }
}

// round 4
// speedup vs baseline: 1.5130x; 1.0920x over previous
#include <cuda_runtime.h>
#include <cuda_fp16.h>
#include <math.h>
#include <stdint.h>

// ---------------- problem constants ----------------
#define B_     2
#define C_     256
#define N_     32768
#define H_     128
#define W_     128
#define HW_    16384
#define NG_    3
#define DEPTH_ 4

// ---------------- device scratch (static, no allocs) ----------------
__device__ float g_grid [B_*C_*HW_];   // scatter grid / conv input
__device__ float g_plane[B_*C_*HW_];   // conv output (rflat)
__device__ float g_skip [B_*C_*HW_];   // plane snapshot from depth 0 (grid 0)
__device__ float g_wpt  [B_*NG_*N_];
__device__ int   g_ci   [B_*NG_*N_];
__device__ float g_counts[B_*NG_*HW_];
__device__ float g_bnm[C_];
__device__ float g_bnr[C_];

// ---------------- mma helper (fp16 x fp16 -> fp32, m16n8k16) ----------------
__device__ __forceinline__ void mma_f16(float d[4], const uint32_t a[4], const uint32_t b[2]) {
    asm volatile(
        "mma.sync.aligned.m16n8k16.row.col.f32.f16.f16.f32 "
        "{%0,%1,%2,%3}, {%4,%5,%6,%7}, {%8,%9}, {%0,%1,%2,%3};\n"
        : "+f"(d[0]), "+f"(d[1]), "+f"(d[2]), "+f"(d[3])
        : "r"(a[0]), "r"(a[1]), "r"(a[2]), "r"(a[3]),
          "r"(b[0]), "r"(b[1]));
}

// ---------------- simple copies ----------------
__global__ void copy4_kernel(const float4* __restrict__ src, float4* __restrict__ dst, int n4) {
    int i = blockIdx.x * blockDim.x + threadIdx.x;
    if (i < n4) dst[i] = src[i];
}
__global__ void save_skip_kernel() {
    int i = blockIdx.x * blockDim.x + threadIdx.x;
    reinterpret_cast<float4*>(g_skip)[i] = reinterpret_cast<const float4*>(g_plane)[i];
}
__global__ void grid_init_kernel(int use_skip) {
    int i = blockIdx.x * blockDim.x + threadIdx.x;
    float4 v;
    if (use_skip) v = reinterpret_cast<const float4*>(g_skip)[i];
    else          v = make_float4(0.f, 0.f, 0.f, 0.f);
    reinterpret_cast<float4*>(g_grid)[i] = v;
}

// ---------------- projection weights (once) ----------------
__global__ void zero_counts_kernel() {
    int i = blockIdx.x * blockDim.x + threadIdx.x;
    if (i < B_*NG_*HW_) g_counts[i] = 0.f;
}
__global__ void count_scatter_kernel(const int* __restrict__ cell_ind,
                                     const float* __restrict__ occ) {
    int i = blockIdx.x * blockDim.x + threadIdx.x;
    if (i >= B_*NG_*N_) return;
    int n = i % N_;
    int g = (i / N_) % NG_;
    int b = i / (NG_*N_);
    int ci = cell_ind[i];
    ci = min(max(ci, 0), HW_ - 1);
    g_ci[i] = ci;
    float o = occ[b*N_ + n];
    atomicAdd(&g_counts[(b*NG_ + g)*HW_ + ci], o*o);
}
__global__ void wpt_kernel(const float* __restrict__ occ) {
    int i = blockIdx.x * blockDim.x + threadIdx.x;
    if (i >= B_*NG_*N_) return;
    int n = i % N_;
    int g = (i / N_) % NG_;
    int b = i / (NG_*N_);
    float o = occ[b*N_ + n];
    float cnt = g_counts[(b*NG_ + g)*HW_ + g_ci[i]];
    g_wpt[i] = o / (o*cnt + 1e-6f);
}

// ---------------- SpatialMix: LN over channels + weighted scatter ----------------
__global__ void ln_scatter_kernel(const float* __restrict__ tokens,
                                  const float* __restrict__ lng,
                                  const float* __restrict__ lnb,
                                  int g) {
    __shared__ float sg[C_], sb[C_];
    int tid = threadIdx.x;
    sg[tid] = lng[tid];
    sb[tid] = lnb[tid];
    __syncthreads();

    int b = blockIdx.y;
    int n = blockIdx.x * 256 + tid;
    const float* tb = tokens + (size_t)b*C_*N_ + n;

    float s = 0.f, ss = 0.f;
    #pragma unroll 8
    for (int c = 0; c < C_; c++) {
        float x = tb[(size_t)c * N_];
        s += x; ss += x * x;
    }
    float m = s * (1.f / C_);
    float rstd = rsqrtf(ss * (1.f / C_) - m*m + 1e-5f);

    int   cell = g_ci [((size_t)b*NG_ + g)*N_ + n];
    float w    = g_wpt[((size_t)b*NG_ + g)*N_ + n];
    float* gb = g_grid + (size_t)b*C_*HW_ + cell;
    #pragma unroll 4
    for (int c = 0; c < C_; c++) {
        float x = tb[(size_t)c * N_];
        float v = ((x - m) * rstd * sg[c] + sb[c]) * w;
        atomicAdd(gb + (size_t)c * HW_, v);
    }
}

// ---------------- fused depthwise conv3x3 -> relu -> conv3x3 ----------------
#define CONV_SMEM (2 * 130 * 132 * 4)
__global__ void dwconv2_kernel(const float* __restrict__ w1, const float* __restrict__ b1,
                               const float* __restrict__ w2, const float* __restrict__ b2) {
    extern __shared__ float sm[];
    float* s0 = sm;
    float* s1 = sm + 130 * 132;

    int bc = blockIdx.x;
    int c  = bc % C_;
    const float* img = g_grid + (size_t)bc * HW_;
    float* out = g_plane + (size_t)bc * HW_;

    for (int i = threadIdx.x; i < 130*132*2; i += blockDim.x) sm[i] = 0.f;
    __syncthreads();
    for (int i = threadIdx.x; i < HW_; i += blockDim.x) {
        int y = i >> 7, x = i & 127;
        s0[(y+1)*132 + (x+1)] = img[i];
    }
    float w[9];
    #pragma unroll
    for (int j = 0; j < 9; j++) w[j] = __ldg(w1 + c*9 + j);
    float bb = __ldg(b1 + c);
    __syncthreads();

    for (int i = threadIdx.x; i < HW_; i += blockDim.x) {
        int y = i >> 7, x = i & 127;
        const float* p = &s0[y*132 + x];
        float acc = bb;
        acc += w[0]*p[0]   + w[1]*p[1]   + w[2]*p[2];
        acc += w[3]*p[132] + w[4]*p[133] + w[5]*p[134];
        acc += w[6]*p[264] + w[7]*p[265] + w[8]*p[266];
        s1[(y+1)*132 + (x+1)] = fmaxf(acc, 0.f);
    }
    #pragma unroll
    for (int j = 0; j < 9; j++) w[j] = __ldg(w2 + c*9 + j);
    bb = __ldg(b2 + c);
    __syncthreads();

    for (int i = threadIdx.x; i < HW_; i += blockDim.x) {
        int y = i >> 7, x = i & 127;
        const float* p = &s1[y*132 + x];
        float acc = bb;
        acc += w[0]*p[0]   + w[1]*p[1]   + w[2]*p[2];
        acc += w[3]*p[132] + w[4]*p[133] + w[5]*p[134];
        acc += w[6]*p[264] + w[7]*p[265] + w[8]*p[266];
        out[i] = acc;
    }
}

// ---------------- BatchNorm (train-mode batch stats), two-pass ----------------
__global__ void bn_stats_kernel(const float* __restrict__ ascale) {
    int c = blockIdx.x;
    float s = __ldg(ascale + c);
    __shared__ float rbuf[256];
    __shared__ float mean_sh;

    float sum = 0.f;
    for (int b = 0; b < B_; b++) {
        const float* p = g_plane + ((size_t)b*C_ + c) * HW_;
        for (int i = threadIdx.x; i < HW_; i += 256) sum += p[i] * s;
    }
    rbuf[threadIdx.x] = sum; __syncthreads();
    for (int o = 128; o > 0; o >>= 1) {
        if (threadIdx.x < o) rbuf[threadIdx.x] += rbuf[threadIdx.x + o];
        __syncthreads();
    }
    if (threadIdx.x == 0) mean_sh = rbuf[0] * (1.f / (B_*HW_));
    __syncthreads();
    float m = mean_sh;

    float vs = 0.f;
    for (int b = 0; b < B_; b++) {
        const float* p = g_plane + ((size_t)b*C_ + c) * HW_;
        for (int i = threadIdx.x; i < HW_; i += 256) {
            float d = p[i] * s - m;
            vs += d * d;
        }
    }
    rbuf[threadIdx.x] = vs; __syncthreads();
    for (int o = 128; o > 0; o >>= 1) {
        if (threadIdx.x < o) rbuf[threadIdx.x] += rbuf[threadIdx.x + o];
        __syncthreads();
    }
    if (threadIdx.x == 0) {
        g_bnm[c] = m;
        g_bnr[c] = rsqrtf(rbuf[0] * (1.f / (B_*HW_)) + 1e-5f);
    }
}

// ---------------- sigmoid gate + gather + residual add ----------------
__global__ void gather_update_kernel(float* __restrict__ tokens, int g,
                                     const float* __restrict__ ascale,
                                     const float* __restrict__ bng,
                                     const float* __restrict__ bnb) {
    int n = blockIdx.x * 256 + threadIdx.x;
    int c = blockIdx.y;
    int b = blockIdx.z;
    int cell = g_ci[((size_t)b*NG_ + g)*N_ + n];
    float p = g_plane[((size_t)b*C_ + c)*HW_ + cell];
    float y = p * __ldg(ascale + c);
    float t = (y - g_bnm[c]) * g_bnr[c] * __ldg(bng + c) + __ldg(bnb + c);
    float att = 1.f / (1.f + expf(-t));
    tokens[((size_t)b*C_ + c)*N_ + n] += att * p;
}

// ---------------- fused ChannelMix: LN -> W1 -> relu -> W2 -> scaled residual ----------------
// fp16 HMMA m16n8k16. Block 256 threads = 8 warps (4 m-warps x 2 n-warps),
// tile M=256 out-ch x NT=64 tokens.
// Xs: fp16 [token n][channel k] as u32 k-pairs, row stride 132 u32
//     (B-fragment LDS bank = 4*gid+tig -> conflict-free).
// Ws: fp16 [m][k-chunk of 32] as u32 pairs, row stride 20 u32
//     (A-fragment LDS bank = 20*gid+tig mod 32 -> all 32 distinct).
#define CM_NT        64
#define XS_STRIDE    132
#define WS_STRIDE    20
#define CM_SMEM_U32  (64*XS_STRIDE + 256*WS_STRIDE + 256 + 256 + 64 + 64 + 256 + 256)
#define CM_SMEM      (CM_SMEM_U32 * 4)

__device__ __forceinline__ void cm_gemm_f16(const float* __restrict__ Wg,
                                            const uint32_t* __restrict__ Xs,
                                            uint32_t* __restrict__ Ws,
                                            int tid, int gid, int tig, int wm, int wn,
                                            float acc[4][4][4]) {
    #pragma unroll
    for (int i = 0; i < 4; i++)
        #pragma unroll
        for (int j = 0; j < 4; j++)
            #pragma unroll
            for (int r = 0; r < 4; r++) acc[i][j][r] = 0.f;

    for (int k0 = 0; k0 < C_; k0 += 32) {
        // prefetch W chunk: row m = tid, k = k0..k0+31 (128B contiguous per thread)
        const float4* wp = reinterpret_cast<const float4*>(Wg + (size_t)tid*C_ + k0);
        uint32_t pk[16];
        #pragma unroll
        for (int q = 0; q < 4; q++) {
            float4 u = wp[2*q], v = wp[2*q+1];
            __half2 h0 = __floats2half2_rn(u.x, u.y);
            __half2 h1 = __floats2half2_rn(u.z, u.w);
            __half2 h2 = __floats2half2_rn(v.x, v.y);
            __half2 h3 = __floats2half2_rn(v.z, v.w);
            pk[4*q+0] = *(uint32_t*)&h0;
            pk[4*q+1] = *(uint32_t*)&h1;
            pk[4*q+2] = *(uint32_t*)&h2;
            pk[4*q+3] = *(uint32_t*)&h3;
        }
        __syncthreads();   // previous chunk fully consumed
        uint4* wd = reinterpret_cast<uint4*>(Ws + tid*WS_STRIDE);   // 80B rows, 16B aligned
        wd[0] = make_uint4(pk[0],  pk[1],  pk[2],  pk[3]);
        wd[1] = make_uint4(pk[4],  pk[5],  pk[6],  pk[7]);
        wd[2] = make_uint4(pk[8],  pk[9],  pk[10], pk[11]);
        wd[3] = make_uint4(pk[12], pk[13], pk[14], pk[15]);
        __syncthreads();

        #pragma unroll
        for (int kk = 0; kk < 2; kk++) {            // two k16 steps per chunk
            uint32_t bfr[4][2];
            #pragma unroll
            for (int j = 0; j < 4; j++) {
                const uint32_t* xr = Xs + (wn + j*8 + gid)*XS_STRIDE + (k0 >> 1) + kk*8;
                bfr[j][0] = xr[tig];
                bfr[j][1] = xr[tig + 4];
            }
            #pragma unroll
            for (int i = 0; i < 4; i++) {
                const uint32_t* w0 = Ws + (wm + i*16 + gid)*WS_STRIDE + kk*8;
                const uint32_t* w1 = w0 + 8*WS_STRIDE;
                uint32_t afr[4];
                afr[0] = w0[tig];
                afr[1] = w1[tig];
                afr[2] = w0[tig + 4];
                afr[3] = w1[tig + 4];
                #pragma unroll
                for (int j = 0; j < 4; j++)
                    mma_f16(acc[i][j], afr, bfr[j]);
            }
        }
    }
}

__global__ void __launch_bounds__(256, 2)
channelmix_kernel(float* __restrict__ tokens,
                  const float* __restrict__ lng, const float* __restrict__ lnb,
                  const float* __restrict__ W1,  const float* __restrict__ b1,
                  const float* __restrict__ W2,  const float* __restrict__ b2,
                  const float* __restrict__ csc) {
    extern __shared__ uint32_t smu[];
    uint32_t* Xs    = smu;                        // [64][132] u32 (fp16 pairs)
    uint32_t* Ws    = Xs + 64*XS_STRIDE;          // [256][20]
    float* red      = (float*)(Ws + 256*WS_STRIDE);   // [4][64]
    float* red2     = red + 256;                  // [4][64]
    float* mean_s   = red2 + 256;                 // [64]
    float* rstd_s   = mean_s + 64;                // [64]
    float* lg       = rstd_s + 64;                // [256]
    float* lb       = lg + 256;                   // [256]
    __half* Xh      = reinterpret_cast<__half*>(Xs);  // [64][264-half rows]

    const int tid  = threadIdx.x;
    const int b    = blockIdx.y;
    const int n0   = blockIdx.x * CM_NT;
    const int lane = tid & 31;
    const int wid  = tid >> 5;
    const int gid  = lane >> 2;
    const int tig  = lane & 3;
    const int wm   = (wid >> 1) * 64;   // warp m base
    const int wn   = (wid & 1)  * 32;   // warp n base

    lg[tid] = lng[tid];
    lb[tid] = lnb[tid];

    // ---- LayerNorm over channels, fp16 X into Xs [n][c] ----
    const int part = tid >> 6;          // 0..3 (c quadrant)
    const int nn   = tid & 63;          // token within tile
    const float* tcol = tokens + (size_t)b*C_*N_ + n0 + nn;
    float s = 0.f, ss = 0.f;
    #pragma unroll 8
    for (int c = part*64; c < part*64 + 64; c++) {
        float x = tcol[(size_t)c * N_];
        s += x; ss += x*x;
    }
    red [part*64 + nn] = s;
    red2[part*64 + nn] = ss;
    __syncthreads();
    if (tid < 64) {
        float sm  = red [tid] + red [64+tid] + red [128+tid] + red [192+tid];
        float sm2 = red2[tid] + red2[64+tid] + red2[128+tid] + red2[192+tid];
        float m = sm * (1.f / C_);
        mean_s[tid] = m;
        rstd_s[tid] = rsqrtf(sm2 * (1.f / C_) - m*m + 1e-5f);
    }
    __syncthreads();
    {
        float m = mean_s[nn], r = rstd_s[nn];
        #pragma unroll 8
        for (int c = part*64; c < part*64 + 64; c++) {
            float x = tcol[(size_t)c * N_];
            Xh[nn*(2*XS_STRIDE) + c] = __float2half((x - m) * r * lg[c] + lb[c]);
        }
    }
    // (cm_gemm_f16 begins with __syncthreads before first staging store)

    float acc[4][4][4];

    // ---------------- GEMM 1: h1 = W1 @ X ----------------
    cm_gemm_f16(W1, Xs, Ws, tid, gid, tig, wm, wn, acc);

    __syncthreads();   // all Xs reads done before overwrite
    #pragma unroll
    for (int i = 0; i < 4; i++) {
        int m0 = wm + i*16 + gid;
        float bva = __ldg(b1 + m0);
        float bvb = __ldg(b1 + m0 + 8);
        #pragma unroll
        for (int j = 0; j < 4; j++) {
            int col = wn + j*8 + 2*tig;
            Xh[ col   *(2*XS_STRIDE) + m0    ] = __float2half(fmaxf(acc[i][j][0] + bva, 0.f));
            Xh[(col+1)*(2*XS_STRIDE) + m0    ] = __float2half(fmaxf(acc[i][j][1] + bva, 0.f));
            Xh[ col   *(2*XS_STRIDE) + m0 + 8] = __float2half(fmaxf(acc[i][j][2] + bvb, 0.f));
            Xh[(col+1)*(2*XS_STRIDE) + m0 + 8] = __float2half(fmaxf(acc[i][j][3] + bvb, 0.f));
        }
    }

    // ---------------- GEMM 2: h2 = W2 @ relu(h1) ----------------
    cm_gemm_f16(W2, Xs, Ws, tid, gid, tig, wm, wn, acc);

    // ---- tokens += (h2 + b2) * scale ----
    #pragma unroll
    for (int i = 0; i < 4; i++) {
        int m0 = wm + i*16 + gid;
        float b2a = __ldg(b2 + m0),     sca = __ldg(csc + m0);
        float b2b = __ldg(b2 + m0 + 8), scb = __ldg(csc + m0 + 8);
        #pragma unroll
        for (int j = 0; j < 4; j++) {
            int col = wn + j*8 + 2*tig;
            float* p0 = tokens + ((size_t)b*C_ + m0    )*N_ + n0 + col;
            float* p1 = tokens + ((size_t)b*C_ + m0 + 8)*N_ + n0 + col;
            float2 t0 = *reinterpret_cast<float2*>(p0);
            float2 t1 = *reinterpret_cast<float2*>(p1);
            t0.x += (acc[i][j][0] + b2a) * sca;
            t0.y += (acc[i][j][1] + b2a) * sca;
            t1.x += (acc[i][j][2] + b2b) * scb;
            t1.y += (acc[i][j][3] + b2b) * scb;
            *reinterpret_cast<float2*>(p0) = t0;
            *reinterpret_cast<float2*>(p1) = t1;
        }
    }
}

// ---------------- launch ----------------
extern "C" void kernel_launch(void* const* d_in, const int* in_sizes, int n_in,
                              void* d_out, int out_size) {
    const float* tokens_in  = (const float*)d_in[0];
    const int*   cell_ind   = (const int*)  d_in[1];
    const float* occ        = (const float*)d_in[2];
    const float* smix_ln_g  = (const float*)d_in[3];
    const float* smix_ln_b  = (const float*)d_in[4];
    const float* ffn_w1     = (const float*)d_in[5];
    const float* ffn_b1     = (const float*)d_in[6];
    const float* ffn_w2     = (const float*)d_in[7];
    const float* ffn_b2     = (const float*)d_in[8];
    const float* att_scale  = (const float*)d_in[9];
    const float* att_bn_g   = (const float*)d_in[10];
    const float* att_bn_b   = (const float*)d_in[11];
    const float* cmix_ln_g  = (const float*)d_in[12];
    const float* cmix_ln_b  = (const float*)d_in[13];
    const float* cmix_w1    = (const float*)d_in[14];
    const float* cmix_b1    = (const float*)d_in[15];
    const float* cmix_w2    = (const float*)d_in[16];
    const float* cmix_b2    = (const float*)d_in[17];
    const float* cmix_scale = (const float*)d_in[18];
    float* tokens = (float*)d_out;

    cudaFuncSetAttribute(dwconv2_kernel,    cudaFuncAttributeMaxDynamicSharedMemorySize, CONV_SMEM);
    cudaFuncSetAttribute(channelmix_kernel, cudaFuncAttributeMaxDynamicSharedMemorySize, CM_SMEM);

    // tokens -> d_out (working buffer)
    copy4_kernel<<<(B_*C_*N_/4 + 255)/256, 256>>>(
        reinterpret_cast<const float4*>(tokens_in),
        reinterpret_cast<float4*>(tokens), B_*C_*N_/4);

    // projection weights (fixed across depths)
    zero_counts_kernel <<<(B_*NG_*HW_ + 255)/256, 256>>>();
    count_scatter_kernel<<<(B_*NG_*N_ + 255)/256, 256>>>(cell_ind, occ);
    wpt_kernel          <<<(B_*NG_*N_ + 255)/256, 256>>>(occ);

    for (int d = 0; d < DEPTH_; d++) {
        int g = d % NG_;
        grid_init_kernel<<<(B_*C_*HW_/4)/256, 256>>>((d == 3 && g == 0) ? 1 : 0);

        ln_scatter_kernel<<<dim3(N_/256, B_), 256>>>(tokens, smix_ln_g + d*C_, smix_ln_b + d*C_, g);

        dwconv2_kernel<<<B_*C_, 256, CONV_SMEM>>>(ffn_w1 + d*C_*9, ffn_b1 + d*C_,
                                                  ffn_w2 + d*C_*9, ffn_b2 + d*C_);
        if (d == 0) save_skip_kernel<<<(B_*C_*HW_/4)/256, 256>>>();

        bn_stats_kernel<<<C_, 256>>>(att_scale + d*C_);

        gather_update_kernel<<<dim3(N_/256, C_, B_), 256>>>(tokens, g,
                                                            att_scale + d*C_,
                                                            att_bn_g + d*C_,
                                                            att_bn_b + d*C_);

        channelmix_kernel<<<dim3(N_/CM_NT, B_), 256, CM_SMEM>>>(
            tokens,
            cmix_ln_g + d*C_, cmix_ln_b + d*C_,
            cmix_w1 + d*C_*C_, cmix_b1 + d*C_,
            cmix_w2 + d*C_*C_, cmix_b2 + d*C_,
            cmix_scale + d*C_);
    }
}